// round 3
// baseline (speedup 1.0000x reference)
#include <cuda_runtime.h>
#include <math.h>

// ---------------- problem constants ----------------
#define TT 128          // timesteps
#define FF 64           // input features
#define H1V 32          // layer1 hidden
#define G1 128          // 4*H1
#define XH1 96          // FF + H1
#define KSPL1 48        // k-split point layer1

#define H2V 16          // layer2 hidden
#define G2 64           // 4*H2
#define XH2 80          // 64 + H2
#define KSPL2 40        // k-split point layer2

#define MAXB 4096

// ---------------- scratch (no cudaMalloc allowed) ----------------
__device__ float g_h1[(size_t)MAXB * TT * 64];  // layer1 bidi output [B][T][64]
__device__ float g_h2[MAXB * 32];               // layer2 concat [B][32]

// ---------------- activations ----------------
__device__ __forceinline__ float sigf(float x) {
    return 1.0f / (1.0f + __expf(-x));
}
__device__ __forceinline__ float tanh_f(float x) {
    return 1.0f - 2.0f / (__expf(2.0f * x) + 1.0f);
}

// ================= layer 1: bidirectional LSTM, H=32, return sequences ================
// grid (B/16, 2), block 128 = 4 warps = 2 sample-groups x 2 k-halves.
// Warp (grp, half): 8 samples of group grp; half 0 reduces k=[0,48)+bias,
// half 1 reduces k=[48,96) and ships partial gate sums through SMEM.
// Half 0 combines, applies activations, owns (h,c), writes h to staging+gmem.
__global__ void __launch_bounds__(128) lstm1_kernel(
    const float* __restrict__ x,
    const float* __restrict__ Wf, const float* __restrict__ Uf, const float* __restrict__ bf,
    const float* __restrict__ Wb, const float* __restrict__ Ub, const float* __restrict__ bb)
{
    extern __shared__ float smem[];
    float* sW  = smem;                       // [96][128]  48KB  [k][elem*4+gate]
    float* sXH = smem + XH1 * G1;            // [16][96]    6KB  staged x|h
    float* sEx = sXH + 16 * XH1;             // [16][128]   8KB  partial z exchange

    const int dir = blockIdx.y;
    const float* W    = dir ? Wb : Wf;
    const float* U    = dir ? Ub : Uf;
    const float* bias = dir ? bb : bf;

    const int tid  = threadIdx.x;
    const int wrp  = tid >> 5;
    const int j    = tid & 31;
    const int grp  = wrp & 1;        // sample group within block
    const int half = wrp >> 1;       // k-half

    // stage combined [W;U] transposed: sW[k*128 + e*4 + g] = src[k][g*32+e]
    for (int idx = tid; idx < XH1 * G1; idx += 128) {
        int k = idx >> 7;
        int c = idx & 127;
        int e = c >> 2, g = c & 3;
        sW[idx] = (k < FF) ? W[k * G1 + g * H1V + e]
                           : U[(k - FF) * G1 + g * H1V + e];
    }

    const int blockSample = blockIdx.x * 16;          // 16 samples per block
    float* xh = sXH + grp * 8 * XH1;                  // this group's staging rows
    float* ex = sEx + grp * 8 * G1;                   // this group's exchange rows

    float bz0 = 0.f, bz1 = 0.f, bz2 = 0.f, bz3 = 0.f;
    float cc[8];
    if (half == 0) {
        bz0 = bias[j]; bz1 = bias[H1V + j];
        bz2 = bias[2 * H1V + j]; bz3 = bias[3 * H1V + j];
        #pragma unroll
        for (int s = 0; s < 8; s++) {
            cc[s] = 0.0f;
            xh[s * XH1 + FF + j] = 0.0f;   // h = 0
        }
    }
    __syncthreads();

    const int kbeg = half ? KSPL1 : 0;
    const float* xbase = x + (size_t)blockSample * TT * FF;

    for (int t = 0; t < TT; t++) {
        const int tt = dir ? (TT - 1 - t) : t;

        // cooperative x staging: 16 samples x 16 float4 = 256, 2 per thread
        #pragma unroll
        for (int r = 0; r < 2; r++) {
            int fl = tid + r * 128;
            int s = fl >> 4, vec = fl & 15;
            *(float4*)&sXH[s * XH1 + vec * 4] =
                *((const float4*)(xbase + ((size_t)s * TT + tt) * FF) + vec);
        }
        __syncthreads();   // bar A: x staged, prev h visible

        float z0[8], z1[8], z2[8], z3[8];
        #pragma unroll
        for (int s = 0; s < 8; s++) {
            z0[s] = bz0; z1[s] = bz1; z2[s] = bz2; z3[s] = bz3;
        }

        #pragma unroll 4
        for (int k4 = kbeg; k4 < kbeg + KSPL1; k4 += 4) {
            const float4 wA = *(const float4*)&sW[(k4 + 0) * G1 + j * 4];
            const float4 wB = *(const float4*)&sW[(k4 + 1) * G1 + j * 4];
            const float4 wC = *(const float4*)&sW[(k4 + 2) * G1 + j * 4];
            const float4 wD = *(const float4*)&sW[(k4 + 3) * G1 + j * 4];
            #pragma unroll
            for (int s = 0; s < 8; s++) {
                const float4 xv = *(const float4*)&xh[s * XH1 + k4];  // broadcast
                z0[s] = fmaf(wA.x, xv.x, z0[s]);
                z1[s] = fmaf(wA.y, xv.x, z1[s]);
                z2[s] = fmaf(wA.z, xv.x, z2[s]);
                z3[s] = fmaf(wA.w, xv.x, z3[s]);
                z0[s] = fmaf(wB.x, xv.y, z0[s]);
                z1[s] = fmaf(wB.y, xv.y, z1[s]);
                z2[s] = fmaf(wB.z, xv.y, z2[s]);
                z3[s] = fmaf(wB.w, xv.y, z3[s]);
                z0[s] = fmaf(wC.x, xv.z, z0[s]);
                z1[s] = fmaf(wC.y, xv.z, z1[s]);
                z2[s] = fmaf(wC.z, xv.z, z2[s]);
                z3[s] = fmaf(wC.w, xv.z, z3[s]);
                z0[s] = fmaf(wD.x, xv.w, z0[s]);
                z1[s] = fmaf(wD.y, xv.w, z1[s]);
                z2[s] = fmaf(wD.z, xv.w, z2[s]);
                z3[s] = fmaf(wD.w, xv.w, z3[s]);
            }
        }

        if (half == 1) {
            #pragma unroll
            for (int s = 0; s < 8; s++) {
                ex[s * G1 +           j] = z0[s];
                ex[s * G1 +  H1V +    j] = z1[s];
                ex[s * G1 + 2*H1V +   j] = z2[s];
                ex[s * G1 + 3*H1V +   j] = z3[s];
            }
        }
        __syncthreads();   // bar B: partials visible

        if (half == 0) {
            float* outp = &g_h1[((size_t)(blockSample + grp * 8) * TT + tt) * 64 + dir * H1V + j];
            #pragma unroll
            for (int s = 0; s < 8; s++) {
                const float zi = z0[s] + ex[s * G1 +          j];
                const float zf = z1[s] + ex[s * G1 +  H1V +   j];
                const float zg = z2[s] + ex[s * G1 + 2*H1V +  j];
                const float zo = z3[s] + ex[s * G1 + 3*H1V +  j];
                const float ig = sigf(zi);
                const float fg = sigf(zf);
                const float gg = tanh_f(zg);
                const float og = sigf(zo);
                cc[s] = fg * cc[s] + ig * gg;
                const float h = og * tanh_f(cc[s]);
                xh[s * XH1 + FF + j] = h;
                outp[(size_t)s * TT * 64] = h;
            }
        }
        // bar A of the next iteration orders h writes before the next reads
    }
}

// ================= layer 2: bidirectional LSTM, H=16, return last h ================
// Same k-split scheme. Lane: e = j&15 gate-elem, hw = j>>4 -> lane serves
// samples hw*4..hw*4+3 of its group's 8.
__global__ void __launch_bounds__(128) lstm2_kernel(
    const float* __restrict__ W2f, const float* __restrict__ U2f, const float* __restrict__ b2f,
    const float* __restrict__ W2b, const float* __restrict__ U2b, const float* __restrict__ b2b)
{
    __shared__ __align__(16) float sW [XH2 * G2];    // 20KB
    __shared__ __align__(16) float sXH[16 * XH2];    // 5KB
    __shared__ __align__(16) float sEx[16 * G2];     // 4KB

    const int dir = blockIdx.y;
    const float* W    = dir ? W2b : W2f;
    const float* U    = dir ? U2b : U2f;
    const float* bias = dir ? b2b : b2f;

    const int tid  = threadIdx.x;
    const int wrp  = tid >> 5;
    const int j    = tid & 31;
    const int grp  = wrp & 1;
    const int half = wrp >> 1;
    const int e    = j & 15;
    const int hw   = j >> 4;

    for (int idx = tid; idx < XH2 * G2; idx += 128) {
        int k = idx >> 6;
        int c = idx & 63;
        int ee = c >> 2, g = c & 3;
        sW[idx] = (k < 64) ? W[k * G2 + g * H2V + ee]
                           : U[(k - 64) * G2 + g * H2V + ee];
    }

    const int blockSample = blockIdx.x * 16;
    float* xh = sXH + grp * 8 * XH2;
    float* ex = sEx + grp * 8 * G2;

    float bz0 = 0.f, bz1 = 0.f, bz2 = 0.f, bz3 = 0.f;
    float cc[4], hh[4];
    if (half == 0) {
        bz0 = bias[e]; bz1 = bias[H2V + e];
        bz2 = bias[2 * H2V + e]; bz3 = bias[3 * H2V + e];
        #pragma unroll
        for (int s = 0; s < 4; s++) {
            cc[s] = 0.0f; hh[s] = 0.0f;
            xh[(hw * 4 + s) * XH2 + 64 + e] = 0.0f;
        }
    }
    __syncthreads();

    const int kbeg = half ? KSPL2 : 0;

    for (int t = 0; t < TT; t++) {
        const int tt = dir ? (TT - 1 - t) : t;

        #pragma unroll
        for (int r = 0; r < 2; r++) {
            int fl = tid + r * 128;
            int s = fl >> 4, vec = fl & 15;
            *(float4*)&sXH[s * XH2 + vec * 4] =
                *((const float4*)(g_h1 + ((size_t)(blockSample + s) * TT + tt) * 64) + vec);
        }
        __syncthreads();   // bar A

        float z0[4], z1[4], z2[4], z3[4];
        #pragma unroll
        for (int s = 0; s < 4; s++) {
            z0[s] = bz0; z1[s] = bz1; z2[s] = bz2; z3[s] = bz3;
        }

        #pragma unroll 5
        for (int k4 = kbeg; k4 < kbeg + KSPL2; k4 += 4) {
            const float4 wA = *(const float4*)&sW[(k4 + 0) * G2 + e * 4];
            const float4 wB = *(const float4*)&sW[(k4 + 1) * G2 + e * 4];
            const float4 wC = *(const float4*)&sW[(k4 + 2) * G2 + e * 4];
            const float4 wD = *(const float4*)&sW[(k4 + 3) * G2 + e * 4];
            #pragma unroll
            for (int s = 0; s < 4; s++) {
                const float4 xv = *(const float4*)&xh[(hw * 4 + s) * XH2 + k4];
                z0[s] = fmaf(wA.x, xv.x, z0[s]);
                z1[s] = fmaf(wA.y, xv.x, z1[s]);
                z2[s] = fmaf(wA.z, xv.x, z2[s]);
                z3[s] = fmaf(wA.w, xv.x, z3[s]);
                z0[s] = fmaf(wB.x, xv.y, z0[s]);
                z1[s] = fmaf(wB.y, xv.y, z1[s]);
                z2[s] = fmaf(wB.z, xv.y, z2[s]);
                z3[s] = fmaf(wB.w, xv.y, z3[s]);
                z0[s] = fmaf(wC.x, xv.z, z0[s]);
                z1[s] = fmaf(wC.y, xv.z, z1[s]);
                z2[s] = fmaf(wC.z, xv.z, z2[s]);
                z3[s] = fmaf(wC.w, xv.z, z3[s]);
                z0[s] = fmaf(wD.x, xv.w, z0[s]);
                z1[s] = fmaf(wD.y, xv.w, z1[s]);
                z2[s] = fmaf(wD.z, xv.w, z2[s]);
                z3[s] = fmaf(wD.w, xv.w, z3[s]);
            }
        }

        if (half == 1) {
            #pragma unroll
            for (int s = 0; s < 4; s++) {
                ex[(hw * 4 + s) * G2 +          e] = z0[s];
                ex[(hw * 4 + s) * G2 +  H2V +   e] = z1[s];
                ex[(hw * 4 + s) * G2 + 2*H2V +  e] = z2[s];
                ex[(hw * 4 + s) * G2 + 3*H2V +  e] = z3[s];
            }
        }
        __syncthreads();   // bar B

        if (half == 0) {
            #pragma unroll
            for (int s = 0; s < 4; s++) {
                const float zi = z0[s] + ex[(hw * 4 + s) * G2 +          e];
                const float zf = z1[s] + ex[(hw * 4 + s) * G2 +  H2V +   e];
                const float zg = z2[s] + ex[(hw * 4 + s) * G2 + 2*H2V +  e];
                const float zo = z3[s] + ex[(hw * 4 + s) * G2 + 3*H2V +  e];
                const float ig = sigf(zi);
                const float fg = sigf(zf);
                const float gg = tanh_f(zg);
                const float og = sigf(zo);
                cc[s] = fg * cc[s] + ig * gg;
                hh[s] = og * tanh_f(cc[s]);
                xh[(hw * 4 + s) * XH2 + 64 + e] = hh[s];
            }
        }
    }

    if (half == 0) {
        #pragma unroll
        for (int s = 0; s < 4; s++)
            g_h2[(blockSample + grp * 8 + hw * 4 + s) * 32 + dir * H2V + e] = hh[s];
    }
}

// ================= head: dense(8)+swish, dense(2)+sigmoid ================
__global__ void head_kernel(
    const float* __restrict__ W3, const float* __restrict__ b3,
    const float* __restrict__ W4, const float* __restrict__ b4,
    float* __restrict__ out, int B)
{
    const int b = blockIdx.x * blockDim.x + threadIdx.x;
    if (b >= B) return;

    float xv[32];
    #pragma unroll
    for (int i = 0; i < 32; i++) xv[i] = g_h2[b * 32 + i];

    float y[8];
    #pragma unroll
    for (int o = 0; o < 8; o++) {
        float acc = b3[o];
        #pragma unroll
        for (int k = 0; k < 32; k++)
            acc = fmaf(xv[k], W3[k * 8 + o], acc);
        y[o] = acc * sigf(acc);   // swish
    }

    #pragma unroll
    for (int m = 0; m < 2; m++) {
        float acc = b4[m];
        #pragma unroll
        for (int o = 0; o < 8; o++)
            acc = fmaf(y[o], W4[o * 2 + m], acc);
        out[b * 2 + m] = sigf(acc);
    }
}

// ================= launch ================
extern "C" void kernel_launch(void* const* d_in, const int* in_sizes, int n_in,
                              void* d_out, int out_size)
{
    const float* x   = (const float*)d_in[0];
    const float* W1f = (const float*)d_in[1];
    const float* U1f = (const float*)d_in[2];
    const float* b1f = (const float*)d_in[3];
    const float* W1b = (const float*)d_in[4];
    const float* U1b = (const float*)d_in[5];
    const float* b1b = (const float*)d_in[6];
    const float* W2f = (const float*)d_in[7];
    const float* U2f = (const float*)d_in[8];
    const float* b2f = (const float*)d_in[9];
    const float* W2b = (const float*)d_in[10];
    const float* U2b = (const float*)d_in[11];
    const float* b2b = (const float*)d_in[12];
    const float* W3  = (const float*)d_in[13];
    const float* b3  = (const float*)d_in[14];
    const float* W4  = (const float*)d_in[15];
    const float* b4  = (const float*)d_in[16];
    float* out = (float*)d_out;

    const int B = in_sizes[0] / (TT * FF);   // 4096

    const int smem1 = (XH1 * G1 + 16 * XH1 + 16 * G1) * (int)sizeof(float);  // 62KB
    cudaFuncSetAttribute(lstm1_kernel, cudaFuncAttributeMaxDynamicSharedMemorySize, smem1);

    lstm1_kernel<<<dim3(B / 16, 2), 128, smem1>>>(
        x, W1f, U1f, b1f, W1b, U1b, b1b);

    lstm2_kernel<<<dim3(B / 16, 2), 128>>>(
        W2f, U2f, b2f, W2b, U2b, b2b);

    head_kernel<<<(B + 255) / 256, 256>>>(W3, b3, W4, b4, out, B);
}

// round 4
// speedup vs baseline: 1.5592x; 1.5592x over previous
#include <cuda_runtime.h>
#include <math.h>

// ---------------- problem constants ----------------
#define TT 128          // timesteps
#define FF 64           // input features
#define H1V 32          // layer1 hidden
#define G1 128          // 4*H1
#define XH1 96          // FF + H1
#define H2V 16          // layer2 hidden
#define G2 64           // 4*H2
#define XH2 80          // 64 + H2
#define MAXB 4096

// ---------------- scratch (no cudaMalloc allowed) ----------------
__device__ float g_h1[(size_t)MAXB * TT * 64];  // layer1 bidi output [B][T][64]
__device__ float g_h2[MAXB * 32];               // layer2 concat [B][32]

typedef unsigned long long u64;

// ---------------- f32x2 helpers ----------------
__device__ __forceinline__ u64 pack2(float a, float b) {
    u64 r; asm("mov.b64 %0, {%1,%2};" : "=l"(r) : "f"(a), "f"(b)); return r;
}
__device__ __forceinline__ u64 dup2(float a) { return pack2(a, a); }
__device__ __forceinline__ void unpack2(u64 v, float &a, float &b) {
    asm("mov.b64 {%0,%1}, %2;" : "=f"(a), "=f"(b) : "l"(v));
}
__device__ __forceinline__ void ffma2(u64 &d, u64 a, u64 b) {
    asm("fma.rn.f32x2 %0, %1, %2, %0;" : "+l"(d) : "l"(a), "l"(b));
}

// ---------------- activations ----------------
__device__ __forceinline__ float sigf(float x) {
    return 1.0f / (1.0f + __expf(-x));
}
__device__ __forceinline__ float tanh_f(float x) {
    return 1.0f - 2.0f / (__expf(2.0f * x) + 1.0f);
}

// ================= layer 1: bidirectional LSTM, H=32, return sequences ================
// grid (B/32, 2), block 128 (4 warps), warp-autonomous (no block barriers in loop).
// Each warp owns 8 samples = 4 f32x2 SAMPLE-PAIRS. Lane j owns gate element j.
// x/h staged in SMEM pair-interleaved: row per pair = 192 floats, [k][2] = (x_s0, x_s1).
// z accumulators are f32x2 pairs; weights dup'd in registers (amortized over 4 pairs).
__global__ void __launch_bounds__(128) lstm1_kernel(
    const float* __restrict__ x,
    const float* __restrict__ Wf, const float* __restrict__ Uf, const float* __restrict__ bf,
    const float* __restrict__ Wb, const float* __restrict__ Ub, const float* __restrict__ bb)
{
    extern __shared__ float smem[];
    float* sW  = smem;                  // [96][128] = 48KB, [k][elem*4+gate]
    float* sXH = smem + XH1 * G1;       // [4 warps][4 pairs][192] = 12KB

    const int dir = blockIdx.y;
    const float* W    = dir ? Wb : Wf;
    const float* U    = dir ? Ub : Uf;
    const float* bias = dir ? bb : bf;

    const int tid = threadIdx.x;
    const int wrp = tid >> 5;
    const int j   = tid & 31;

    // stage combined [W;U] transposed: sW[k*128 + e*4 + g] = src[k][g*32+e]
    for (int idx = tid; idx < XH1 * G1; idx += 128) {
        int k = idx >> 7;
        int c = idx & 127;
        int e = c >> 2, g = c & 3;
        sW[idx] = (k < FF) ? W[k * G1 + g * H1V + e]
                           : U[(k - FF) * G1 + g * H1V + e];
    }
    __syncthreads();

    const u64 bzi = dup2(bias[j]);
    const u64 bzf = dup2(bias[H1V + j]);
    const u64 bzg = dup2(bias[2 * H1V + j]);
    const u64 bzo = dup2(bias[3 * H1V + j]);

    const int warpSample = (blockIdx.x * 4 + wrp) * 8;
    float* xh = sXH + wrp * (4 * 192);    // 4 pair-rows of 192 floats

    float cc[8];
    #pragma unroll
    for (int s = 0; s < 8; s++) cc[s] = 0.0f;
    #pragma unroll
    for (int p = 0; p < 4; p++)
        *(float2*)&xh[p * 192 + (FF + j) * 2] = make_float2(0.0f, 0.0f);  // h = 0
    __syncwarp();

    const float* xb = x + (size_t)warpSample * TT * FF;

    for (int t = 0; t < TT; t++) {
        const int tt = dir ? (TT - 1 - t) : t;

        // stage x_t pair-interleaved: 64 (pair,quad) tasks, 2 per lane.
        #pragma unroll
        for (int r = 0; r < 2; r++) {
            const int idx = j + r * 32;
            const int p = idx >> 4;
            const int q = idx & 15;
            const float4 v0 = *((const float4*)(xb + ((size_t)(2 * p)     * TT + tt) * FF) + q);
            const float4 v1 = *((const float4*)(xb + ((size_t)(2 * p + 1) * TT + tt) * FF) + q);
            float* dst = &xh[p * 192 + q * 8];
            *(float4*)dst       = make_float4(v0.x, v1.x, v0.y, v1.y);
            *(float4*)(dst + 4) = make_float4(v0.z, v1.z, v0.w, v1.w);
        }
        __syncwarp();   // x staged; prev-step h writes visible

        u64 zi[4], zf[4], zg[4], zo[4];
        #pragma unroll
        for (int p = 0; p < 4; p++) { zi[p] = bzi; zf[p] = bzf; zg[p] = bzg; zo[p] = bzo; }

        #pragma unroll 4
        for (int k = 0; k < XH1; k += 2) {
            const float4 wA = *(const float4*)&sW[k       * G1 + j * 4];
            const float4 wB = *(const float4*)&sW[(k + 1) * G1 + j * 4];
            const u64 wi0 = dup2(wA.x), wf0 = dup2(wA.y), wg0 = dup2(wA.z), wo0 = dup2(wA.w);
            const u64 wi1 = dup2(wB.x), wf1 = dup2(wB.y), wg1 = dup2(wB.z), wo1 = dup2(wB.w);
            #pragma unroll
            for (int p = 0; p < 4; p++) {
                const ulonglong2 xp = *(const ulonglong2*)&xh[p * 192 + k * 2];
                ffma2(zi[p], wi0, xp.x); ffma2(zf[p], wf0, xp.x);
                ffma2(zg[p], wg0, xp.x); ffma2(zo[p], wo0, xp.x);
                ffma2(zi[p], wi1, xp.y); ffma2(zf[p], wf1, xp.y);
                ffma2(zg[p], wg1, xp.y); ffma2(zo[p], wo1, xp.y);
            }
        }

        __syncwarp();   // all lanes done reading x/h of this step

        float* outp = &g_h1[((size_t)warpSample * TT + tt) * 64 + dir * H1V + j];
        #pragma unroll
        for (int p = 0; p < 4; p++) {
            float zia, zib, zfa, zfb, zga, zgb, zoa, zob;
            unpack2(zi[p], zia, zib); unpack2(zf[p], zfa, zfb);
            unpack2(zg[p], zga, zgb); unpack2(zo[p], zoa, zob);
            const float c0 = sigf(zfa) * cc[2 * p]     + sigf(zia) * tanh_f(zga);
            const float c1 = sigf(zfb) * cc[2 * p + 1] + sigf(zib) * tanh_f(zgb);
            const float h0 = sigf(zoa) * tanh_f(c0);
            const float h1 = sigf(zob) * tanh_f(c1);
            cc[2 * p]     = c0;
            cc[2 * p + 1] = c1;
            *(float2*)&xh[p * 192 + (FF + j) * 2] = make_float2(h0, h1);
            outp[(size_t)(2 * p)     * TT * 64] = h0;
            outp[(size_t)(2 * p + 1) * TT * 64] = h1;
        }
        // next iteration's post-staging __syncwarp orders h writes vs reads
    }
}

// ================= layer 2: bidirectional LSTM, H=16, return last h ================
// Same scheme. Lane: e = j&15 gate-elem, hw = j>>4; lane serves pairs hw*2, hw*2+1
// (samples hw*4 .. hw*4+3). grid (B/32, 2), block 128.
__global__ void __launch_bounds__(128) lstm2_kernel(
    const float* __restrict__ W2f, const float* __restrict__ U2f, const float* __restrict__ b2f,
    const float* __restrict__ W2b, const float* __restrict__ U2b, const float* __restrict__ b2b)
{
    __shared__ __align__(16) float sW [XH2 * G2];       // 20KB
    __shared__ __align__(16) float sXH[4 * 4 * 160];    // 10KB: [warp][pair][160]

    const int dir = blockIdx.y;
    const float* W    = dir ? W2b : W2f;
    const float* U    = dir ? U2b : U2f;
    const float* bias = dir ? b2b : b2f;

    const int tid = threadIdx.x;
    const int wrp = tid >> 5;
    const int j   = tid & 31;
    const int e   = j & 15;
    const int hw  = j >> 4;

    for (int idx = tid; idx < XH2 * G2; idx += 128) {
        int k = idx >> 6;
        int c = idx & 63;
        int ee = c >> 2, g = c & 3;
        sW[idx] = (k < 64) ? W[k * G2 + g * H2V + ee]
                           : U[(k - 64) * G2 + g * H2V + ee];
    }
    __syncthreads();

    const u64 bzi = dup2(bias[e]);
    const u64 bzf = dup2(bias[H2V + e]);
    const u64 bzg = dup2(bias[2 * H2V + e]);
    const u64 bzo = dup2(bias[3 * H2V + e]);

    const int warpSample = (blockIdx.x * 4 + wrp) * 8;
    float* xh = sXH + wrp * (4 * 160);

    float cc[4], hres[4];
    #pragma unroll
    for (int s = 0; s < 4; s++) { cc[s] = 0.0f; hres[s] = 0.0f; }
    #pragma unroll
    for (int pp = 0; pp < 2; pp++)
        *(float2*)&xh[(hw * 2 + pp) * 160 + (64 + e) * 2] = make_float2(0.0f, 0.0f);
    __syncwarp();

    for (int t = 0; t < TT; t++) {
        const int tt = dir ? (TT - 1 - t) : t;

        // stage layer1 output pair-interleaved (all 32 lanes cover all 4 pairs)
        #pragma unroll
        for (int r = 0; r < 2; r++) {
            const int idx = j + r * 32;
            const int p = idx >> 4;
            const int q = idx & 15;
            const float4 v0 = *((const float4*)(g_h1 + ((size_t)(warpSample + 2 * p)     * TT + tt) * 64) + q);
            const float4 v1 = *((const float4*)(g_h1 + ((size_t)(warpSample + 2 * p + 1) * TT + tt) * 64) + q);
            float* dst = &xh[p * 160 + q * 8];
            *(float4*)dst       = make_float4(v0.x, v1.x, v0.y, v1.y);
            *(float4*)(dst + 4) = make_float4(v0.z, v1.z, v0.w, v1.w);
        }
        __syncwarp();

        u64 zi[2], zf[2], zg[2], zo[2];
        #pragma unroll
        for (int pp = 0; pp < 2; pp++) { zi[pp] = bzi; zf[pp] = bzf; zg[pp] = bzg; zo[pp] = bzo; }

        #pragma unroll 4
        for (int k = 0; k < XH2; k += 2) {
            const float4 wA = *(const float4*)&sW[k       * G2 + e * 4];
            const float4 wB = *(const float4*)&sW[(k + 1) * G2 + e * 4];
            const u64 wi0 = dup2(wA.x), wf0 = dup2(wA.y), wg0 = dup2(wA.z), wo0 = dup2(wA.w);
            const u64 wi1 = dup2(wB.x), wf1 = dup2(wB.y), wg1 = dup2(wB.z), wo1 = dup2(wB.w);
            #pragma unroll
            for (int pp = 0; pp < 2; pp++) {
                const ulonglong2 xp = *(const ulonglong2*)&xh[(hw * 2 + pp) * 160 + k * 2];
                ffma2(zi[pp], wi0, xp.x); ffma2(zf[pp], wf0, xp.x);
                ffma2(zg[pp], wg0, xp.x); ffma2(zo[pp], wo0, xp.x);
                ffma2(zi[pp], wi1, xp.y); ffma2(zf[pp], wf1, xp.y);
                ffma2(zg[pp], wg1, xp.y); ffma2(zo[pp], wo1, xp.y);
            }
        }

        __syncwarp();

        #pragma unroll
        for (int pp = 0; pp < 2; pp++) {
            float zia, zib, zfa, zfb, zga, zgb, zoa, zob;
            unpack2(zi[pp], zia, zib); unpack2(zf[pp], zfa, zfb);
            unpack2(zg[pp], zga, zgb); unpack2(zo[pp], zoa, zob);
            const float c0 = sigf(zfa) * cc[2 * pp]     + sigf(zia) * tanh_f(zga);
            const float c1 = sigf(zfb) * cc[2 * pp + 1] + sigf(zib) * tanh_f(zgb);
            const float h0 = sigf(zoa) * tanh_f(c0);
            const float h1 = sigf(zob) * tanh_f(c1);
            cc[2 * pp]     = c0;
            cc[2 * pp + 1] = c1;
            hres[2 * pp]     = h0;
            hres[2 * pp + 1] = h1;
            *(float2*)&xh[(hw * 2 + pp) * 160 + (64 + e) * 2] = make_float2(h0, h1);
        }
    }

    // final h: fwd -> cols [0,16), bwd -> cols [16,32)
    #pragma unroll
    for (int s = 0; s < 4; s++)
        g_h2[(warpSample + hw * 4 + s) * 32 + dir * H2V + e] = hres[s];
}

// ================= head: dense(8)+swish, dense(2)+sigmoid ================
__global__ void head_kernel(
    const float* __restrict__ W3, const float* __restrict__ b3,
    const float* __restrict__ W4, const float* __restrict__ b4,
    float* __restrict__ out, int B)
{
    const int b = blockIdx.x * blockDim.x + threadIdx.x;
    if (b >= B) return;

    float xv[32];
    #pragma unroll
    for (int i = 0; i < 32; i++) xv[i] = g_h2[b * 32 + i];

    float y[8];
    #pragma unroll
    for (int o = 0; o < 8; o++) {
        float acc = b3[o];
        #pragma unroll
        for (int k = 0; k < 32; k++)
            acc = fmaf(xv[k], W3[k * 8 + o], acc);
        y[o] = acc * sigf(acc);   // swish
    }

    #pragma unroll
    for (int m = 0; m < 2; m++) {
        float acc = b4[m];
        #pragma unroll
        for (int o = 0; o < 8; o++)
            acc = fmaf(y[o], W4[o * 2 + m], acc);
        out[b * 2 + m] = sigf(acc);
    }
}

// ================= launch ================
extern "C" void kernel_launch(void* const* d_in, const int* in_sizes, int n_in,
                              void* d_out, int out_size)
{
    const float* x   = (const float*)d_in[0];
    const float* W1f = (const float*)d_in[1];
    const float* U1f = (const float*)d_in[2];
    const float* b1f = (const float*)d_in[3];
    const float* W1b = (const float*)d_in[4];
    const float* U1b = (const float*)d_in[5];
    const float* b1b = (const float*)d_in[6];
    const float* W2f = (const float*)d_in[7];
    const float* U2f = (const float*)d_in[8];
    const float* b2f = (const float*)d_in[9];
    const float* W2b = (const float*)d_in[10];
    const float* U2b = (const float*)d_in[11];
    const float* b2b = (const float*)d_in[12];
    const float* W3  = (const float*)d_in[13];
    const float* b3  = (const float*)d_in[14];
    const float* W4  = (const float*)d_in[15];
    const float* b4  = (const float*)d_in[16];
    float* out = (float*)d_out;

    const int B = in_sizes[0] / (TT * FF);   // 4096

    const int smem1 = (XH1 * G1 + 4 * 4 * 192) * (int)sizeof(float);  // 60KB
    cudaFuncSetAttribute(lstm1_kernel, cudaFuncAttributeMaxDynamicSharedMemorySize, smem1);

    lstm1_kernel<<<dim3(B / 32, 2), 128, smem1>>>(
        x, W1f, U1f, b1f, W1b, U1b, b1b);

    lstm2_kernel<<<dim3(B / 32, 2), 128>>>(
        W2f, U2f, b2f, W2b, U2b, b2b);

    head_kernel<<<(B + 255) / 256, 256>>>(W3, b3, W4, b4, out, B);
}

// round 5
// speedup vs baseline: 3.7627x; 2.4132x over previous
#include <cuda_runtime.h>
#include <math.h>
#include <stdint.h>

// ---------------- problem constants ----------------
#define TT 128
#define MAXB 4096

// ---------------- scratch (no cudaMalloc allowed) ----------------
__device__ float g_h1[(size_t)MAXB * TT * 64];  // layer1 bidi output [B][T][64]
__device__ float g_h2[MAXB * 32];               // layer2 concat [B][32]

// ---------------- helpers ----------------
__device__ __forceinline__ uint32_t tf32c(float x) {
    uint32_t r; asm("cvt.rna.tf32.f32 %0, %1;" : "=r"(r) : "f"(x)); return r;
}
__device__ __forceinline__ float tanhx(float x) {
    float y; asm("tanh.approx.f32 %0, %1;" : "=f"(y) : "f"(x)); return y;
}
__device__ __forceinline__ float sigx(float x) {
    return fmaf(tanhx(x * 0.5f), 0.5f, 0.5f);
}
__device__ __forceinline__ void mma_tf32(float* d, const uint4& a, uint32_t b0, uint32_t b1) {
    asm volatile(
        "mma.sync.aligned.m16n8k8.row.col.f32.tf32.tf32.f32 "
        "{%0,%1,%2,%3},{%4,%5,%6,%7},{%8,%9},{%0,%1,%2,%3};"
        : "+f"(d[0]), "+f"(d[1]), "+f"(d[2]), "+f"(d[3])
        : "r"(a.x), "r"(a.y), "r"(a.z), "r"(a.w), "r"(b0), "r"(b1));
}

// ================= templated LSTM layer on tensor cores =================
// KIN: per-step input width (64). H: hidden (32 or 16). SEQ_OUT: write full
// sequence to g_h1 vs only last h to g_h2.
//
// One warp owns 16 samples. z[16, 4H] computed as m16n8k8 tf32 MMAs over
// K = KIN+H. Weights [K][4H] live in SMEM in B-fragment layout (built once).
// x_t and h_{t-1} live in SMEM in A-fragment layout; h is written back each
// step by the activation phase (warp-autonomous, __syncwarp only).
//
// Fragment maps (PTX m16n8k8, gid=lane>>2, tig=lane&3):
//   A: a0=(gid,tig) a1=(gid+8,tig) a2=(gid,tig+4) a3=(gid+8,tig+4)
//   B: b0=(k=tig,n=gid) b1=(k=tig+4,n=gid)
//   D: c0=(gid,2tig) c1=(gid,2tig+1) c2=(gid+8,2tig) c3=(gid+8,2tig+1)
template <int KIN, int H, bool SEQ_OUT>
__global__ void __launch_bounds__(128) lstm_mma_kernel(
    const float* __restrict__ in,   // [B][T][64]
    const float* __restrict__ Wf, const float* __restrict__ Uf, const float* __restrict__ bf,
    const float* __restrict__ Wb, const float* __restrict__ Ub, const float* __restrict__ bb)
{
    constexpr int KTOT  = KIN + H;       // 96 / 80
    constexpr int KC    = KTOT / 8;      // 12 / 10
    constexpr int NGATE = 4 * H;         // 128 / 64
    constexpr int NT    = NGATE / 8;     // 16 / 8
    constexpr int NTH   = H / 8;         // 4 / 2
    constexpr int KCH   = KIN / 8;       // 8 (h kchunks start here)

    extern __shared__ float smem[];
    float*    Bsm    = smem;                          // [KC][NT/2][32][4]
    float*    biasSm = Bsm + KC * (NT / 2) * 128;     // [NGATE]
    float*    Asm    = biasSm + NGATE;                // [4 warps][KC][32][4]
    float*    houtS  = Asm + 4 * KC * 128;            // [4][16][36] (SEQ only)

    const int dir = blockIdx.y;
    const float* W    = dir ? Wb : Wf;
    const float* U    = dir ? Ub : Uf;
    const float* bias = dir ? bb : bf;

    const int tid = threadIdx.x;
    const int wrp = tid >> 5;
    const int j   = tid & 31;
    const int gid = j >> 2;
    const int tig = j & 3;

    // ---- build B fragments + bias in smem (once) ----
    for (int idx = tid; idx < KC * (NT / 2) * 128; idx += 128) {
        const int slot = idx & 3;
        const int lane = (idx >> 2) & 31;
        const int ntp  = (idx >> 7) % (NT / 2);
        const int kc   = idx / (128 * (NT / 2));
        const int nt    = ntp * 2 + (slot >> 1);
        const int which = slot & 1;
        const int k = kc * 8 + (lane & 3) + which * 4;
        const int n = nt * 8 + (lane >> 2);
        const float v = (k < KIN) ? W[k * NGATE + n] : U[(k - KIN) * NGATE + n];
        ((uint32_t*)Bsm)[idx] = tf32c(v);
    }
    for (int idx = tid; idx < NGATE; idx += 128) biasSm[idx] = bias[idx];
    __syncthreads();

    // ---- per-warp state ----
    float* Aw = Asm + wrp * KC * 128;          // this warp's A-fragment region
    const int ws = (blockIdx.x * 4 + wrp) * 16; // first sample of this warp

    // zero the h region (kchunks KCH..KC)
    for (int i = j; i < (KC - KCH) * 128; i += 32) Aw[KCH * 128 + i] = 0.0f;
    __syncwarp();

    float cc[NTH][4];
    #pragma unroll
    for (int nt = 0; nt < NTH; nt++)
        #pragma unroll
        for (int p = 0; p < 4; p++) cc[nt][p] = 0.0f;

    // producer mapping for x staging: lane handles sample sP, k-half khalf
    const int sP     = j >> 1;
    const int khalf  = j & 1;
    const int rhP    = j >> 4;       // sP >> 3
    // byte offset of this lane's STS base within Aw
    char* AwB = (char*)Aw;
    const int prodBase = khalf * 2048 + ((sP & 7) * 4) * 16 + rhP * 4;

    const float* xbase = in + (size_t)(ws + sP) * TT * 64 + khalf * 32;

    // prefetch x for t = 0
    float4 xr[8];
    {
        const int tt0 = dir ? (TT - 1) : 0;
        #pragma unroll
        for (int q = 0; q < 8; q++)
            xr[q] = *(const float4*)(xbase + (size_t)tt0 * 64 + q * 4);
    }

    for (int t = 0; t < TT; t++) {
        const int tt = dir ? (TT - 1 - t) : t;

        // ---- 1. store x_t into A-fragment layout; prefetch x_{t+1} ----
        #pragma unroll
        for (int q = 0; q < 8; q++) {
            const int off = prodBase + (q >> 1) * 512 + (q & 1) * 8;
            *(uint32_t*)(AwB + off)      = tf32c(xr[q].x);
            *(uint32_t*)(AwB + off + 16) = tf32c(xr[q].y);
            *(uint32_t*)(AwB + off + 32) = tf32c(xr[q].z);
            *(uint32_t*)(AwB + off + 48) = tf32c(xr[q].w);
        }
        if (t + 1 < TT) {
            const int ttn = dir ? (tt - 1) : (tt + 1);
            #pragma unroll
            for (int q = 0; q < 8; q++)
                xr[q] = *(const float4*)(xbase + (size_t)ttn * 64 + q * 4);
        }
        __syncwarp();   // x_t + h_{t-1} visible

        // ---- 2. z = [x|h] @ [W;U] + b via MMA ----
        float d[NT][4];
        #pragma unroll
        for (int nt = 0; nt < NT; nt++) {
            const float2 bb2 = *(const float2*)&biasSm[nt * 8 + 2 * tig];
            d[nt][0] = bb2.x; d[nt][1] = bb2.y;
            d[nt][2] = bb2.x; d[nt][3] = bb2.y;
        }
        const uint4* Bq = (const uint4*)Bsm;
        #pragma unroll
        for (int kc = 0; kc < KC; kc++) {
            const uint4 a = *(const uint4*)(AwB + kc * 512 + j * 16);
            #pragma unroll
            for (int ntp = 0; ntp < NT / 2; ntp++) {
                const uint4 b = Bq[(kc * (NT / 2) + ntp) * 32 + j];
                mma_tf32(d[2 * ntp],     a, b.x, b.y);
                mma_tf32(d[2 * ntp + 1], a, b.z, b.w);
            }
        }
        __syncwarp();   // all lanes done reading A before h/x overwrite

        // ---- 3. activations, h feedback, output ----
        #pragma unroll
        for (int nt = 0; nt < NTH; nt++) {
            #pragma unroll
            for (int p = 0; p < 4; p++) {
                const float zi = d[nt][p];
                const float zf = d[NTH + nt][p];
                const float zg = d[2 * NTH + nt][p];
                const float zo = d[3 * NTH + nt][p];
                const float ig = sigx(zi);
                const float fg = sigx(zf);
                const float gg = tanhx(zg);
                const float og = sigx(zo);
                const float c  = fg * cc[nt][p] + ig * gg;
                const float h  = og * tanhx(c);
                cc[nt][p] = c;

                const int rh = p >> 1;     // row half: gid vs gid+8
                const int b  = p & 1;      // column parity
                const int e  = nt * 8 + 2 * tig + b;   // h element index
                // h -> A-fragment layout (k = KIN + e)
                const int lane2 = gid * 4 + (tig & 1) * 2 + b;
                const int slot2 = rh + 2 * (tig >> 1);
                Aw[(KCH + nt) * 128 + lane2 * 4 + slot2] = __uint_as_float(tf32c(h));

                if (SEQ_OUT) {
                    houtS[wrp * 576 + (gid + 8 * rh) * 36 + e] = h;
                } else if (t == TT - 1) {
                    g_h2[(ws + gid + 8 * rh) * 32 + dir * H + e] = h;
                }
            }
        }

        if (SEQ_OUT) {
            __syncwarp();   // hout complete
            const int s  = j >> 1;
            const int eh = (j & 1) * 16;
            float* hw = &houtS[wrp * 576 + s * 36 + eh];
            float* gp = &g_h1[((size_t)(ws + s) * TT + tt) * 64 + dir * 32 + eh];
            #pragma unroll
            for (int i = 0; i < 4; i++)
                *(float4*)(gp + i * 4) = *(const float4*)(hw + i * 4);
        }
        // next iteration's __syncwarp (after x STS) publishes h writes
    }
}

// ================= head: dense(8)+swish, dense(2)+sigmoid ================
__device__ __forceinline__ float sigf(float x) { return 1.0f / (1.0f + __expf(-x)); }

__global__ void head_kernel(
    const float* __restrict__ W3, const float* __restrict__ b3,
    const float* __restrict__ W4, const float* __restrict__ b4,
    float* __restrict__ out, int B)
{
    const int b = blockIdx.x * blockDim.x + threadIdx.x;
    if (b >= B) return;

    float xv[32];
    #pragma unroll
    for (int i = 0; i < 32; i++) xv[i] = g_h2[b * 32 + i];

    float y[8];
    #pragma unroll
    for (int o = 0; o < 8; o++) {
        float acc = b3[o];
        #pragma unroll
        for (int k = 0; k < 32; k++)
            acc = fmaf(xv[k], W3[k * 8 + o], acc);
        y[o] = acc * sigf(acc);   // swish
    }

    #pragma unroll
    for (int m = 0; m < 2; m++) {
        float acc = b4[m];
        #pragma unroll
        for (int o = 0; o < 8; o++)
            acc = fmaf(y[o], W4[o * 2 + m], acc);
        out[b * 2 + m] = sigf(acc);
    }
}

// ================= launch ================
extern "C" void kernel_launch(void* const* d_in, const int* in_sizes, int n_in,
                              void* d_out, int out_size)
{
    const float* x   = (const float*)d_in[0];
    const float* W1f = (const float*)d_in[1];
    const float* U1f = (const float*)d_in[2];
    const float* b1f = (const float*)d_in[3];
    const float* W1b = (const float*)d_in[4];
    const float* U1b = (const float*)d_in[5];
    const float* b1b = (const float*)d_in[6];
    const float* W2f = (const float*)d_in[7];
    const float* U2f = (const float*)d_in[8];
    const float* b2f = (const float*)d_in[9];
    const float* W2b = (const float*)d_in[10];
    const float* U2b = (const float*)d_in[11];
    const float* b2b = (const float*)d_in[12];
    const float* W3  = (const float*)d_in[13];
    const float* b3  = (const float*)d_in[14];
    const float* W4  = (const float*)d_in[15];
    const float* b4  = (const float*)d_in[16];
    float* out = (float*)d_out;

    const int B = in_sizes[0] / (TT * 64);   // 4096

    // layer 1: KIN=64, H=32, SEQ_OUT
    {
        constexpr int KC = 12, NT = 16, NGATE = 128;
        const int smemB = (KC * (NT / 2) * 128 + NGATE + 4 * KC * 128 + 4 * 576)
                          * (int)sizeof(float);   // ~83.5 KB
        cudaFuncSetAttribute(lstm_mma_kernel<64, 32, true>,
                             cudaFuncAttributeMaxDynamicSharedMemorySize, smemB);
        lstm_mma_kernel<64, 32, true><<<dim3(B / 64, 2), 128, smemB>>>(
            x, W1f, U1f, b1f, W1b, U1b, b1b);
    }

    // layer 2: KIN=64 (bidi concat), H=16, last-h only; input = g_h1
    {
        constexpr int KC = 10, NT = 8, NGATE = 64;
        const int smemB = (KC * (NT / 2) * 128 + NGATE + 4 * KC * 128)
                          * (int)sizeof(float);   // ~40.5 KB
        cudaFuncSetAttribute(lstm_mma_kernel<64, 16, false>,
                             cudaFuncAttributeMaxDynamicSharedMemorySize, smemB);
        float* h1ptr;
        cudaGetSymbolAddress((void**)&h1ptr, g_h1);
        lstm_mma_kernel<64, 16, false><<<dim3(B / 64, 2), 128, smemB>>>(
            h1ptr, W2f, U2f, b2f, W2b, U2b, b2b);
    }

    head_kernel<<<(B + 255) / 256, 256>>>(W3, b3, W4, b4, out, B);
}

// round 6
// speedup vs baseline: 3.9174x; 1.0411x over previous
#include <cuda_runtime.h>
#include <math.h>
#include <stdint.h>

// ---------------- problem constants ----------------
#define TT 128
#define MAXB 4096

// ---------------- scratch (no cudaMalloc allowed) ----------------
__device__ float g_h1[(size_t)MAXB * TT * 64];  // layer1 bidi output [B][T][64]
__device__ float g_h2[MAXB * 32];               // layer2 concat [B][32]

// ---------------- helpers ----------------
__device__ __forceinline__ uint32_t tf32c(float x) {
    uint32_t r; asm("cvt.rna.tf32.f32 %0, %1;" : "=r"(r) : "f"(x)); return r;
}
__device__ __forceinline__ float tanhx(float x) {
    float y; asm("tanh.approx.f32 %0, %1;" : "=f"(y) : "f"(x)); return y;
}
__device__ __forceinline__ float sigx(float x) {
    return fmaf(tanhx(x * 0.5f), 0.5f, 0.5f);
}
__device__ __forceinline__ void mma_tf32(float* d, const uint4& a, uint32_t b0, uint32_t b1) {
    asm volatile(
        "mma.sync.aligned.m16n8k8.row.col.f32.tf32.tf32.f32 "
        "{%0,%1,%2,%3},{%4,%5,%6,%7},{%8,%9},{%0,%1,%2,%3};"
        : "+f"(d[0]), "+f"(d[1]), "+f"(d[2]), "+f"(d[3])
        : "r"(a.x), "r"(a.y), "r"(a.z), "r"(a.w), "r"(b0), "r"(b1));
}

// pair barrier: 2 warps (64 threads), named barrier id (1 or 2; 0 = __syncthreads)
#define BARP(id) asm volatile("bar.sync %0, 64;" :: "r"(id) : "memory")

// ================= split-N tensor-core LSTM layer =================
// One PAIR of warps owns 16 samples. Warp `half` computes the gate columns
// feeding h elements [half*H/2, (half+1)*H/2): per gate g, nt tiles
// g*(H/8) + half*NTM + m, m in [0,NTM). For H=32 that's the even/odd uint4
// of the B smem layout; for H=16 the low/high 8B of each uint4.
// A-tile (x_t | h_{t-1}) is shared by the pair; h-feedback and x staging are
// split; two named pair-barriers per step order A writes vs MMA reads.
//
// Fragment maps (m16n8k8, gid=lane>>2, tig=lane&3):
//   A slots: s0=(gid,tig) s1=(gid+8,tig) s2=(gid,tig+4) s3=(gid+8,tig+4)
//   B: b0=(k=tig,n=gid), b1=(k=tig+4,n=gid)
//   D: c0=(gid,2tig) c1=(gid,2tig+1) c2=(gid+8,2tig) c3=(gid+8,2tig+1)
template <int KIN, int H, bool SEQ_OUT>
__global__ void __launch_bounds__(128) lstm_mma_kernel(
    const float* __restrict__ in,   // [B][T][64]
    const float* __restrict__ Wf, const float* __restrict__ Uf, const float* __restrict__ bf,
    const float* __restrict__ Wb, const float* __restrict__ Ub, const float* __restrict__ bb)
{
    constexpr int KTOT  = KIN + H;       // 96 / 80
    constexpr int KC    = KTOT / 8;      // 12 / 10
    constexpr int NGATE = 4 * H;         // 128 / 64
    constexpr int NT    = NGATE / 8;     // 16 / 8
    constexpr int NTM   = H / 16;        // nt per gate per warp: 2 / 1
    constexpr int KCH   = KIN / 8;       // 8

    extern __shared__ float smem[];
    float* Bsm    = smem;                          // [KC][NT/2][32][4]
    float* biasSm = Bsm + KC * (NT / 2) * 128;     // [NGATE]
    float* Asm    = biasSm + NGATE;                // [2 pairs][KC][32][4]
    float* houtS  = Asm + 2 * KC * 128;            // [2 pairs][16][36] (SEQ only)

    const int dir = blockIdx.y;
    const float* W    = dir ? Wb : Wf;
    const float* U    = dir ? Ub : Uf;
    const float* bias = dir ? bb : bf;

    const int tid = threadIdx.x;
    const int wrp = tid >> 5;
    const int j   = tid & 31;
    const int gid = j >> 2;
    const int tig = j & 3;

    const int pairId = wrp >> 1;
    const int half   = wrp & 1;
    const int barId  = pairId + 1;

    // ---- build B fragments + bias; zero A (once) ----
    for (int idx = tid; idx < KC * (NT / 2) * 128; idx += 128) {
        const int slot = idx & 3;
        const int lane = (idx >> 2) & 31;
        const int ntp  = (idx >> 7) % (NT / 2);
        const int kc   = idx / (128 * (NT / 2));
        const int nt    = ntp * 2 + (slot >> 1);
        const int which = slot & 1;
        const int k = kc * 8 + (lane & 3) + which * 4;
        const int n = nt * 8 + (lane >> 2);
        const float v = (k < KIN) ? W[k * NGATE + n] : U[(k - KIN) * NGATE + n];
        ((uint32_t*)Bsm)[idx] = tf32c(v);
    }
    for (int idx = tid; idx < NGATE; idx += 128) biasSm[idx] = bias[idx];
    for (int idx = tid; idx < 2 * KC * 128; idx += 128) Asm[idx] = 0.0f;
    __syncthreads();

    // ---- per-warp state ----
    float* Aw    = Asm + pairId * KC * 128;
    float* houtW = houtS + pairId * (16 * 36);
    const int ws = (blockIdx.x * 2 + pairId) * 16;

    float2 bz[4][NTM];
    #pragma unroll
    for (int g = 0; g < 4; g++)
        #pragma unroll
        for (int m = 0; m < NTM; m++) {
            const int col = g * H + (half * NTM + m) * 8 + 2 * tig;
            bz[g][m] = make_float2(biasSm[col], biasSm[col + 1]);
        }

    float cc[NTM][4];
    #pragma unroll
    for (int m = 0; m < NTM; m++)
        #pragma unroll
        for (int p = 0; p < 4; p++) cc[m][p] = 0.0f;

    // x-staging mapping: lane handles sample sP, quad-half qh of this warp's
    // k-half (warp stages k in [half*32, half*32+32))
    const int sP  = j >> 1;
    const int qh  = j & 1;
    const int rhP = j >> 4;
    char* AwB = (char*)Aw;
    const int prodBase = half * 2048 + (sP & 7) * 64 + rhP * 4;
    const float* xbase = in + (size_t)(ws + sP) * TT * 64 + half * 32 + qh * 16;

    // prefetch x for t = 0
    float4 xr[4];
    {
        const int tt0 = dir ? (TT - 1) : 0;
        #pragma unroll
        for (int r = 0; r < 4; r++)
            xr[r] = *((const float4*)(xbase + (size_t)tt0 * 64) + r);
    }

    const uint4* Bq  = (const uint4*)Bsm;
    const uint2* Bq2 = (const uint2*)Bsm;

    for (int t = 0; t < TT; t++) {
        const int tt = dir ? (TT - 1 - t) : t;

        // ---- 1. store x_t into A-fragment layout; prefetch x_{t+1} ----
        #pragma unroll
        for (int r = 0; r < 4; r++) {
            const int off = prodBase + ((qh * 2 + (r >> 1)) << 9) + ((r & 1) << 3);
            *(uint32_t*)(AwB + off)      = tf32c(xr[r].x);
            *(uint32_t*)(AwB + off + 16) = tf32c(xr[r].y);
            *(uint32_t*)(AwB + off + 32) = tf32c(xr[r].z);
            *(uint32_t*)(AwB + off + 48) = tf32c(xr[r].w);
        }
        if (t + 1 < TT) {
            const int ttn = dir ? (tt - 1) : (tt + 1);
            #pragma unroll
            for (int r = 0; r < 4; r++)
                xr[r] = *((const float4*)(xbase + (size_t)ttn * 64) + r);
        }
        BARP(barId);   // publishes x_t + h_{t-1} + houtS(t-1) across the pair

        // ---- 1b. flush previous step's h sequence to gmem ----
        if (SEQ_OUT && t > 0) {
            const int tprev = dir ? (tt + 1) : (tt - 1);
            const int sl = half * 8 + (j >> 2);
            const int q0 = j & 3;
            float* gp = &g_h1[((size_t)(ws + sl) * TT + tprev) * 64 + dir * H];
            *(float4*)(gp + q0 * 4)       = *(const float4*)&houtW[sl * 36 + q0 * 4];
            *(float4*)(gp + (q0 + 4) * 4) = *(const float4*)&houtW[sl * 36 + (q0 + 4) * 4];
        }

        // ---- 2. z = [x|h] @ [W;U] + b (this warp's gate columns) ----
        float d[4][NTM][4];
        #pragma unroll
        for (int g = 0; g < 4; g++)
            #pragma unroll
            for (int m = 0; m < NTM; m++) {
                d[g][m][0] = bz[g][m].x; d[g][m][1] = bz[g][m].y;
                d[g][m][2] = bz[g][m].x; d[g][m][3] = bz[g][m].y;
            }
        #pragma unroll
        for (int kc = 0; kc < KC; kc++) {
            const uint4 a = *(const uint4*)(AwB + kc * 512 + j * 16);
            #pragma unroll
            for (int g = 0; g < 4; g++) {
                if constexpr (NTM == 2) {
                    const uint4 b = Bq[(kc * (NT / 2) + g * 2 + half) * 32 + j];
                    mma_tf32(d[g][0], a, b.x, b.y);
                    mma_tf32(d[g][1], a, b.z, b.w);
                } else {
                    const uint2 b2 = Bq2[((kc * (NT / 2) + g) * 32 + j) * 2 + half];
                    mma_tf32(d[g][0], a, b2.x, b2.y);
                }
            }
        }
        BARP(barId);   // both warps finished reading A

        // ---- 3. activations, h feedback, output ----
        #pragma unroll
        for (int m = 0; m < NTM; m++) {
            #pragma unroll
            for (int p = 0; p < 4; p++) {
                const float zi = d[0][m][p];
                const float zf = d[1][m][p];
                const float zg = d[2][m][p];
                const float zo = d[3][m][p];
                const float ig = sigx(zi);
                const float fg = sigx(zf);
                const float gg = tanhx(zg);
                const float og = sigx(zo);
                const float c  = fg * cc[m][p] + ig * gg;
                const float h  = og * tanhx(c);
                cc[m][p] = c;

                const int rh = p >> 1;
                const int b  = p & 1;
                const int e  = (half * NTM + m) * 8 + 2 * tig + b;  // in [0,H)
                const int lane2 = gid * 4 + (tig & 1) * 2 + b;
                const int slot2 = rh + 2 * (tig >> 1);
                Aw[(KCH + half * NTM + m) * 128 + lane2 * 4 + slot2]
                    = __uint_as_float(tf32c(h));

                if (SEQ_OUT) {
                    houtW[(gid + 8 * rh) * 36 + e] = h;
                } else if (t == TT - 1) {
                    g_h2[(ws + gid + 8 * rh) * 32 + dir * H + e] = h;
                }
            }
        }
    }

    BARP(barId);
    if (SEQ_OUT) {   // flush last step
        const int tlast = dir ? 0 : (TT - 1);
        const int sl = half * 8 + (j >> 2);
        const int q0 = j & 3;
        float* gp = &g_h1[((size_t)(ws + sl) * TT + tlast) * 64 + dir * H];
        *(float4*)(gp + q0 * 4)       = *(const float4*)&houtW[sl * 36 + q0 * 4];
        *(float4*)(gp + (q0 + 4) * 4) = *(const float4*)&houtW[sl * 36 + (q0 + 4) * 4];
    }
}

// ================= head: dense(8)+swish, dense(2)+sigmoid ================
__device__ __forceinline__ float sigf(float x) { return 1.0f / (1.0f + __expf(-x)); }

__global__ void head_kernel(
    const float* __restrict__ W3, const float* __restrict__ b3,
    const float* __restrict__ W4, const float* __restrict__ b4,
    float* __restrict__ out, int B)
{
    const int b = blockIdx.x * blockDim.x + threadIdx.x;
    if (b >= B) return;

    float xv[32];
    #pragma unroll
    for (int i = 0; i < 32; i++) xv[i] = g_h2[b * 32 + i];

    float y[8];
    #pragma unroll
    for (int o = 0; o < 8; o++) {
        float acc = b3[o];
        #pragma unroll
        for (int k = 0; k < 32; k++)
            acc = fmaf(xv[k], W3[k * 8 + o], acc);
        y[o] = acc * sigf(acc);   // swish
    }

    #pragma unroll
    for (int m = 0; m < 2; m++) {
        float acc = b4[m];
        #pragma unroll
        for (int o = 0; o < 8; o++)
            acc = fmaf(y[o], W4[o * 2 + m], acc);
        out[b * 2 + m] = sigf(acc);
    }
}

// ================= launch ================
extern "C" void kernel_launch(void* const* d_in, const int* in_sizes, int n_in,
                              void* d_out, int out_size)
{
    const float* x   = (const float*)d_in[0];
    const float* W1f = (const float*)d_in[1];
    const float* U1f = (const float*)d_in[2];
    const float* b1f = (const float*)d_in[3];
    const float* W1b = (const float*)d_in[4];
    const float* U1b = (const float*)d_in[5];
    const float* b1b = (const float*)d_in[6];
    const float* W2f = (const float*)d_in[7];
    const float* U2f = (const float*)d_in[8];
    const float* b2f = (const float*)d_in[9];
    const float* W2b = (const float*)d_in[10];
    const float* U2b = (const float*)d_in[11];
    const float* b2b = (const float*)d_in[12];
    const float* W3  = (const float*)d_in[13];
    const float* b3  = (const float*)d_in[14];
    const float* W4  = (const float*)d_in[15];
    const float* b4  = (const float*)d_in[16];
    float* out = (float*)d_out;

    const int B = in_sizes[0] / (TT * 64);   // 4096

    // layer 1: KIN=64, H=32, SEQ_OUT. 2 pairs (32 samples) per 128-thread block.
    {
        constexpr int KC = 12, NT = 16, NGATE = 128;
        const int smemB = (KC * (NT / 2) * 128 + NGATE + 2 * KC * 128 + 2 * 16 * 36)
                          * (int)sizeof(float);   // ~65 KB -> 2 blocks/SM
        cudaFuncSetAttribute(lstm_mma_kernel<64, 32, true>,
                             cudaFuncAttributeMaxDynamicSharedMemorySize, smemB);
        lstm_mma_kernel<64, 32, true><<<dim3(B / 32, 2), 128, smemB>>>(
            x, W1f, U1f, b1f, W1b, U1b, b1b);
    }

    // layer 2: KIN=64 (bidi concat), H=16, last-h only; input = g_h1
    {
        constexpr int KC = 10, NT = 8, NGATE = 64;
        const int smemB = (KC * (NT / 2) * 128 + NGATE + 2 * KC * 128)
                          * (int)sizeof(float);   // ~30 KB
        cudaFuncSetAttribute(lstm_mma_kernel<64, 16, false>,
                             cudaFuncAttributeMaxDynamicSharedMemorySize, smemB);
        float* h1ptr;
        cudaGetSymbolAddress((void**)&h1ptr, g_h1);
        lstm_mma_kernel<64, 16, false><<<dim3(B / 32, 2), 128, smemB>>>(
            h1ptr, W2f, U2f, b2f, W2b, U2b, b2b);
    }

    head_kernel<<<(B + 255) / 256, 256>>>(W3, b3, W4, b4, out, B);
}

// round 7
// speedup vs baseline: 7.2452x; 1.8495x over previous
#include <cuda_runtime.h>
#include <stdint.h>

#define TT 128
#define MAXB 4096

// ---------------- scratch ----------------
__device__ float g_h1[(size_t)MAXB * TT * 64];  // layer1 bidi output [B][T][64]
__device__ float g_h2[MAXB * 32];               // layer2 concat [B][32]

// ---------------- helpers ----------------
__device__ __forceinline__ uint32_t bf2(float lo, float hi) {
    uint32_t r;
    asm("cvt.rn.bf16x2.f32 %0, %1, %2;" : "=r"(r) : "f"(hi), "f"(lo));
    return r;
}
__device__ __forceinline__ float tanhx(float x) {
    float y; asm("tanh.approx.f32 %0, %1;" : "=f"(y) : "f"(x)); return y;
}
__device__ __forceinline__ float sigx(float x) {
    return fmaf(tanhx(x * 0.5f), 0.5f, 0.5f);
}
__device__ __forceinline__ void mma_bf16(float* d, const uint4& a, uint32_t b0, uint32_t b1) {
    asm volatile(
        "mma.sync.aligned.m16n8k16.row.col.f32.bf16.bf16.f32 "
        "{%0,%1,%2,%3},{%4,%5,%6,%7},{%8,%9},{%0,%1,%2,%3};"
        : "+f"(d[0]), "+f"(d[1]), "+f"(d[2]), "+f"(d[3])
        : "r"(a.x), "r"(a.y), "r"(a.z), "r"(a.w), "r"(b0), "r"(b1));
}
#define BARP(id) asm volatile("bar.sync %0, 64;" :: "r"(id) : "memory")

// ================= layer 1: H=32, KIN=64, K=96 (KC=6 k16-chunks), seq out =====
// Block = 128 threads = 4 warps = ONE group of 16 samples; grid (B/16, 2).
// Warp q computes h elements [q*8, q*8+8): per gate g the n-tile g*4+q.
// B fragments (bf16) in REGISTERS (24 uint2/warp). A tile (x_t|h) in smem,
// 16B/lane/kchunk. Two __syncthreads per step.
__global__ void __launch_bounds__(128) lstm1_mma(
    const float* __restrict__ in,
    const float* __restrict__ Wf, const float* __restrict__ Uf, const float* __restrict__ bf_,
    const float* __restrict__ Wb, const float* __restrict__ Ub, const float* __restrict__ bb)
{
    __shared__ uint32_t Bsm[6 * 16 * 32 * 2];              // 24KB (init only)
    __shared__ __align__(16) uint32_t Asm[6 * 32 * 4];     // 3KB
    __shared__ __align__(16) float houtS[16 * 36];         // 2.25KB
    __shared__ float biasS[128];

    const int dir = blockIdx.y;
    const float* W    = dir ? Wb : Wf;
    const float* U    = dir ? Ub : Uf;
    const float* bias = dir ? bb : bf_;

    const int tid = threadIdx.x;
    const int q   = tid >> 5;          // warp = n-split index
    const int j   = tid & 31;
    const int gid = j >> 2;
    const int tig = j & 3;

    // ---- build B fragments (bf16) ----
    for (int idx = tid; idx < 6 * 16 * 32 * 2; idx += 128) {
        const int which = idx & 1;
        const int lane  = (idx >> 1) & 31;
        const int nt    = (idx >> 6) & 15;
        const int kc    = idx >> 10;
        const int k = kc * 16 + which * 8 + 2 * (lane & 3);
        const int n = nt * 8 + (lane >> 2);
        const float v0 = (k     < 64) ? W[k * 128 + n]       : U[(k - 64) * 128 + n];
        const float v1 = (k + 1 < 64) ? W[(k + 1) * 128 + n] : U[(k - 63) * 128 + n];
        Bsm[idx] = bf2(v0, v1);
    }
    if (tid < 128) biasS[tid] = bias[tid];
    // zero h region of A (kc 4,5)
    for (int idx = tid; idx < 256; idx += 128) Asm[512 + idx] = 0;
    __syncthreads();

    // ---- B to registers: warp q, nt = g*4+q ----
    uint32_t Br[6][4][2];
    #pragma unroll
    for (int kc = 0; kc < 6; kc++)
        #pragma unroll
        for (int g = 0; g < 4; g++) {
            const int base = ((kc * 16 + g * 4 + q) * 32 + j) * 2;
            Br[kc][g][0] = Bsm[base];
            Br[kc][g][1] = Bsm[base + 1];
        }

    float2 bz[4];
    #pragma unroll
    for (int g = 0; g < 4; g++) {
        const int col = g * 32 + q * 8 + 2 * tig;
        bz[g] = make_float2(biasS[col], biasS[col + 1]);
    }

    // ---- x staging mapping: thread -> (sample sP, octet oc) ----
    const int ws  = blockIdx.x * 16;
    const int sP  = tid >> 3;
    const int oc  = tid & 7;
    const int kcP = oc >> 1, chP = oc & 1, rhP = sP >> 3, gidP = sP & 7;
    uint32_t* Ax = Asm + kcP * 128 + gidP * 16 + ((chP << 1) | rhP);
    const float* xb = in + (size_t)(ws + sP) * TT * 64 + oc * 8;

    float cc[4] = {0.f, 0.f, 0.f, 0.f};

    float4 xv0, xv1;
    {
        const int tt0 = dir ? TT - 1 : 0;
        xv0 = *(const float4*)(xb + (size_t)tt0 * 64);
        xv1 = *(const float4*)(xb + (size_t)tt0 * 64 + 4);
    }

    for (int t = 0; t < TT; t++) {
        const int tt = dir ? TT - 1 - t : t;

        // 1. stage x_t (4 STS.32, scattered into A-fragment layout)
        Ax[0]  = bf2(xv0.x, xv0.y);
        Ax[4]  = bf2(xv0.z, xv0.w);
        Ax[8]  = bf2(xv1.x, xv1.y);
        Ax[12] = bf2(xv1.z, xv1.w);
        __syncthreads();   // A complete (x_t + h_{t-1}); hout(t-1) complete

        // 1b. flush hout(t-1) to gmem
        if (t > 0) {
            const int tprev = dir ? tt + 1 : tt - 1;
            const float4 hv = *(const float4*)&houtS[sP * 36 + oc * 4];
            *(float4*)&g_h1[((size_t)(ws + sP) * TT + tprev) * 64 + dir * 32 + oc * 4] = hv;
        }
        // prefetch x_{t+1}
        if (t + 1 < TT) {
            const int ttn = dir ? tt - 1 : tt + 1;
            xv0 = *(const float4*)(xb + (size_t)ttn * 64);
            xv1 = *(const float4*)(xb + (size_t)ttn * 64 + 4);
        }

        // 2. z = [x|h]@[W;U] + b for this warp's 8 columns per gate
        float d[4][4];
        #pragma unroll
        for (int g = 0; g < 4; g++) {
            d[g][0] = bz[g].x; d[g][1] = bz[g].y;
            d[g][2] = bz[g].x; d[g][3] = bz[g].y;
        }
        #pragma unroll
        for (int kc = 0; kc < 6; kc++) {
            const uint4 a = *((const uint4*)Asm + kc * 32 + j);
            #pragma unroll
            for (int g = 0; g < 4; g++)
                mma_bf16(d[g], a, Br[kc][g][0], Br[kc][g][1]);
        }
        __syncthreads();   // A consumed by all warps

        // 3. activations + h feedback + hout
        #pragma unroll
        for (int rh = 0; rh < 2; rh++) {
            float hpair[2];
            #pragma unroll
            for (int b = 0; b < 2; b++) {
                const int p = rh * 2 + b;
                const float ig = sigx(d[0][p]);
                const float fg = sigx(d[1][p]);
                const float gg = tanhx(d[2][p]);
                const float og = sigx(d[3][p]);
                const float c  = fg * cc[p] + ig * gg;
                hpair[b] = og * tanhx(c);
                cc[p] = c;
            }
            // h -> A (k = 64 + q*8 + 2tig + b): kc = 4+(q>>1), lane2 = j
            Asm[(4 + (q >> 1)) * 128 + j * 4 + (((q & 1) << 1) | rh)] = bf2(hpair[0], hpair[1]);
            *(float2*)&houtS[(gid + 8 * rh) * 36 + q * 8 + 2 * tig] = make_float2(hpair[0], hpair[1]);
        }
    }

    __syncthreads();
    {   // final flush
        const int tlast = dir ? 0 : TT - 1;
        const float4 hv = *(const float4*)&houtS[sP * 36 + oc * 4];
        *(float4*)&g_h1[((size_t)(ws + sP) * TT + tlast) * 64 + dir * 32 + oc * 4] = hv;
    }
}

// ================= layer 2: H=16, KIN=64, K=80 (KC=5), last-h only ===========
// Block = 128 threads = 2 warp-PAIRS, each pair owns 16 samples; grid (B/32, 2).
// Warp half computes h elements [half*8, half*8+8): per gate g the n-tile g*2+half.
// B in registers (20 uint2/warp). Named pair barriers.
__global__ void __launch_bounds__(128) lstm2_mma(
    const float* __restrict__ W2f, const float* __restrict__ U2f, const float* __restrict__ b2f,
    const float* __restrict__ W2b, const float* __restrict__ U2b, const float* __restrict__ b2b)
{
    __shared__ uint32_t Bsm[5 * 8 * 32 * 2];               // 10KB (init only)
    __shared__ __align__(16) uint32_t Asm[2 * 5 * 32 * 4]; // 5KB: [pair][kc][lane][4]
    __shared__ float biasS[64];

    const int dir = blockIdx.y;
    const float* W    = dir ? W2b : W2f;
    const float* U    = dir ? U2b : U2f;
    const float* bias = dir ? b2b : b2f;

    const int tid  = threadIdx.x;
    const int wrp  = tid >> 5;
    const int j    = tid & 31;
    const int gid  = j >> 2;
    const int tig  = j & 3;
    const int pair = wrp >> 1;
    const int half = wrp & 1;
    const int barId = pair + 1;

    for (int idx = tid; idx < 5 * 8 * 32 * 2; idx += 128) {
        const int which = idx & 1;
        const int lane  = (idx >> 1) & 31;
        const int nt    = (idx >> 6) & 7;
        const int kc    = idx >> 9;
        const int k = kc * 16 + which * 8 + 2 * (lane & 3);
        const int n = nt * 8 + (lane >> 2);
        const float v0 = (k     < 64) ? W[k * 64 + n]       : U[(k - 64) * 64 + n];
        const float v1 = (k + 1 < 64) ? W[(k + 1) * 64 + n] : U[(k - 63) * 64 + n];
        Bsm[idx] = bf2(v0, v1);
    }
    if (tid < 64) biasS[tid] = bias[tid];
    // zero h regions (kc 4 of each pair)
    for (int idx = tid; idx < 256; idx += 128) {
        const int pp = idx >> 7, ii = idx & 127;
        Asm[pp * 640 + 512 + ii] = 0;
    }
    __syncthreads();

    uint32_t Br[5][4][2];
    #pragma unroll
    for (int kc = 0; kc < 5; kc++)
        #pragma unroll
        for (int g = 0; g < 4; g++) {
            const int base = ((kc * 8 + g * 2 + half) * 32 + j) * 2;
            Br[kc][g][0] = Bsm[base];
            Br[kc][g][1] = Bsm[base + 1];
        }

    float2 bz[4];
    #pragma unroll
    for (int g = 0; g < 4; g++) {
        const int col = g * 16 + half * 8 + 2 * tig;
        bz[g] = make_float2(biasS[col], biasS[col + 1]);
    }

    const int ws = (blockIdx.x * 2 + pair) * 16;
    uint32_t* Aw = Asm + pair * 640;

    // staging: pair-thread ptid -> sample sP, kchunk m (covers both chalfs)
    const int ptid = tid & 63;
    const int sP = ptid >> 2;
    const int m  = ptid & 3;
    const int rhP = sP >> 3, gidP = sP & 7;
    uint32_t* Ax0 = Aw + m * 128 + gidP * 16 + rhP;        // chalf 0
    uint32_t* Ax1 = Ax0 + 2;                               // chalf 1
    const float* xb = (const float*)g_h1 + (size_t)(ws + sP) * TT * 64 + m * 16;

    float cc[4] = {0.f, 0.f, 0.f, 0.f};

    float4 xv[4];
    {
        const int tt0 = dir ? TT - 1 : 0;
        #pragma unroll
        for (int r = 0; r < 4; r++)
            xv[r] = *((const float4*)(xb + (size_t)tt0 * 64) + r);
    }

    for (int t = 0; t < TT; t++) {
        const int tt = dir ? TT - 1 - t : t;

        Ax0[0]  = bf2(xv[0].x, xv[0].y);
        Ax0[4]  = bf2(xv[0].z, xv[0].w);
        Ax0[8]  = bf2(xv[1].x, xv[1].y);
        Ax0[12] = bf2(xv[1].z, xv[1].w);
        Ax1[0]  = bf2(xv[2].x, xv[2].y);
        Ax1[4]  = bf2(xv[2].z, xv[2].w);
        Ax1[8]  = bf2(xv[3].x, xv[3].y);
        Ax1[12] = bf2(xv[3].z, xv[3].w);
        BARP(barId);   // A complete across the pair

        if (t + 1 < TT) {
            const int ttn = dir ? tt - 1 : tt + 1;
            #pragma unroll
            for (int r = 0; r < 4; r++)
                xv[r] = *((const float4*)(xb + (size_t)ttn * 64) + r);
        }

        float d[4][4];
        #pragma unroll
        for (int g = 0; g < 4; g++) {
            d[g][0] = bz[g].x; d[g][1] = bz[g].y;
            d[g][2] = bz[g].x; d[g][3] = bz[g].y;
        }
        #pragma unroll
        for (int kc = 0; kc < 5; kc++) {
            const uint4 a = *((const uint4*)Aw + kc * 32 + j);
            #pragma unroll
            for (int g = 0; g < 4; g++)
                mma_bf16(d[g], a, Br[kc][g][0], Br[kc][g][1]);
        }
        BARP(barId);   // A consumed

        #pragma unroll
        for (int rh = 0; rh < 2; rh++) {
            float hpair[2];
            #pragma unroll
            for (int b = 0; b < 2; b++) {
                const int p = rh * 2 + b;
                const float ig = sigx(d[0][p]);
                const float fg = sigx(d[1][p]);
                const float gg = tanhx(d[2][p]);
                const float og = sigx(d[3][p]);
                const float c  = fg * cc[p] + ig * gg;
                hpair[b] = og * tanhx(c);
                cc[p] = c;
            }
            Aw[512 + j * 4 + ((half << 1) | rh)] = bf2(hpair[0], hpair[1]);
            if (t == TT - 1) {
                const int e0 = half * 8 + 2 * tig;
                *(float2*)&g_h2[(ws + gid + 8 * rh) * 32 + dir * 16 + e0]
                    = make_float2(hpair[0], hpair[1]);
            }
        }
    }
}

// ================= head: dense(8)+swish, dense(2)+sigmoid ================
__device__ __forceinline__ float sigf(float x) { return 1.0f / (1.0f + __expf(-x)); }

__global__ void head_kernel(
    const float* __restrict__ W3, const float* __restrict__ b3,
    const float* __restrict__ W4, const float* __restrict__ b4,
    float* __restrict__ out, int B)
{
    const int b = blockIdx.x * blockDim.x + threadIdx.x;
    if (b >= B) return;

    float xvv[32];
    #pragma unroll
    for (int i = 0; i < 32; i++) xvv[i] = g_h2[b * 32 + i];

    float y[8];
    #pragma unroll
    for (int o = 0; o < 8; o++) {
        float acc = b3[o];
        #pragma unroll
        for (int k = 0; k < 32; k++)
            acc = fmaf(xvv[k], W3[k * 8 + o], acc);
        y[o] = acc * sigf(acc);
    }

    #pragma unroll
    for (int m = 0; m < 2; m++) {
        float acc = b4[m];
        #pragma unroll
        for (int o = 0; o < 8; o++)
            acc = fmaf(y[o], W4[o * 2 + m], acc);
        out[b * 2 + m] = sigf(acc);
    }
}

// ================= launch ================
extern "C" void kernel_launch(void* const* d_in, const int* in_sizes, int n_in,
                              void* d_out, int out_size)
{
    const float* x   = (const float*)d_in[0];
    const float* W1f = (const float*)d_in[1];
    const float* U1f = (const float*)d_in[2];
    const float* b1f = (const float*)d_in[3];
    const float* W1b = (const float*)d_in[4];
    const float* U1b = (const float*)d_in[5];
    const float* b1b = (const float*)d_in[6];
    const float* W2f = (const float*)d_in[7];
    const float* U2f = (const float*)d_in[8];
    const float* b2f = (const float*)d_in[9];
    const float* W2b = (const float*)d_in[10];
    const float* U2b = (const float*)d_in[11];
    const float* b2b = (const float*)d_in[12];
    const float* W3  = (const float*)d_in[13];
    const float* b3  = (const float*)d_in[14];
    const float* W4  = (const float*)d_in[15];
    const float* b4  = (const float*)d_in[16];
    float* out = (float*)d_out;

    const int B = in_sizes[0] / (TT * 64);   // 4096

    lstm1_mma<<<dim3(B / 16, 2), 128>>>(x, W1f, U1f, b1f, W1b, U1b, b1b);
    lstm2_mma<<<dim3(B / 32, 2), 128>>>(W2f, U2f, b2f, W2b, U2b, b2b);
    head_kernel<<<(B + 255) / 256, 256>>>(W3, b3, W4, b4, out, B);
}

// round 8
// speedup vs baseline: 9.5949x; 1.3243x over previous
#include <cuda_runtime.h>
#include <stdint.h>

#define TT 128
#define MAXB 4096

// ---------------- scratch ----------------
__device__ uint32_t g_h1b[(size_t)MAXB * TT * 32];  // layer1 bidi out, bf16x2 [B][T][32]
__device__ float    g_h2[MAXB * 32];                // layer2 concat [B][32]

// ---------------- helpers ----------------
__device__ __forceinline__ uint32_t bf2(float lo, float hi) {
    uint32_t r;
    asm("cvt.rn.bf16x2.f32 %0, %1, %2;" : "=r"(r) : "f"(hi), "f"(lo));
    return r;
}
__device__ __forceinline__ uint32_t bf2p(float2 v) { return bf2(v.x, v.y); }
__device__ __forceinline__ float tanhx(float x) {
    float y; asm("tanh.approx.f32 %0, %1;" : "=f"(y) : "f"(x)); return y;
}
__device__ __forceinline__ float sigx(float x) {
    return fmaf(tanhx(x * 0.5f), 0.5f, 0.5f);
}
__device__ __forceinline__ void mma_bf16(float* d, const uint4& a, uint32_t b0, uint32_t b1) {
    asm volatile(
        "mma.sync.aligned.m16n8k16.row.col.f32.bf16.bf16.f32 "
        "{%0,%1,%2,%3},{%4,%5,%6,%7},{%8,%9},{%0,%1,%2,%3};"
        : "+f"(d[0]), "+f"(d[1]), "+f"(d[2]), "+f"(d[3])
        : "r"(a.x), "r"(a.y), "r"(a.z), "r"(a.w), "r"(b0), "r"(b1));
}
#define BARP(id) asm volatile("bar.sync %0, 64;" :: "r"(id) : "memory")

// ================= layer 1: H=32, KIN=64, K=96 (KC=6), seq out (bf16) ========
// Block = 128 thr = 4 warps = one 16-sample group; grid (B/16, 2).
// Warp q: gate n-tiles g*4+q (h elements [q*8, q*8+8)). B fragments in regs.
// A (x_t|h_{t-1}) double-buffered in smem; ONE __syncthreads per step.
// Staging: warp w builds kc=w fragments; each lane one full uint4 -> STS.128.
__global__ void __launch_bounds__(128) lstm1_mma(
    const float* __restrict__ in,
    const float* __restrict__ Wf, const float* __restrict__ Uf, const float* __restrict__ bf_,
    const float* __restrict__ Wb, const float* __restrict__ Ub, const float* __restrict__ bb)
{
    __shared__ uint32_t Bsm[6 * 16 * 32 * 2];               // 24KB (init only)
    __shared__ __align__(16) uint32_t Asm[2 * 6 * 32 * 4];  // 6KB, 2 buffers
    __shared__ __align__(16) uint32_t houtS[2 * 16 * 18];   // 2.25KB, 2 buffers
    __shared__ float biasS[128];

    const int dir = blockIdx.y;
    const float* W    = dir ? Wb : Wf;
    const float* U    = dir ? Ub : Uf;
    const float* bias = dir ? bb : bf_;

    const int tid = threadIdx.x;
    const int q   = tid >> 5;          // warp id = n-split index = staging kc
    const int l   = tid & 31;
    const int gid = l >> 2;
    const int tig = l & 3;

    // ---- build B fragments (bf16) ----
    for (int idx = tid; idx < 6 * 16 * 32 * 2; idx += 128) {
        const int which = idx & 1;
        const int lane  = (idx >> 1) & 31;
        const int nt    = (idx >> 6) & 15;
        const int kc    = idx >> 10;
        const int k = kc * 16 + which * 8 + 2 * (lane & 3);
        const int n = nt * 8 + (lane >> 2);
        const float v0 = (k     < 64) ? W[k * 128 + n]       : U[(k - 64) * 128 + n];
        const float v1 = (k + 1 < 64) ? W[(k + 1) * 128 + n] : U[(k - 63) * 128 + n];
        Bsm[idx] = bf2(v0, v1);
    }
    if (tid < 128) biasS[tid] = bias[tid];
    // zero h region of buffer 0 (kc 4,5)
    for (int idx = tid; idx < 256; idx += 128) Asm[512 + idx] = 0;
    __syncthreads();

    // ---- B to registers ----
    uint32_t Br[6][4][2];
    #pragma unroll
    for (int kc = 0; kc < 6; kc++)
        #pragma unroll
        for (int g = 0; g < 4; g++) {
            const int base = ((kc * 16 + g * 4 + q) * 32 + l) * 2;
            Br[kc][g][0] = Bsm[base];
            Br[kc][g][1] = Bsm[base + 1];
        }

    float2 bz[4];
    #pragma unroll
    for (int g = 0; g < 4; g++) {
        const int col = g * 32 + q * 8 + 2 * tig;
        bz[g] = make_float2(biasS[col], biasS[col + 1]);
    }

    // ---- staging pointers: warp q stages kc=q (x region kc 0..3) ----
    const int ws = blockIdx.x * 16;
    const float* xs0 = in + (size_t)(ws + gid) * TT * 64 + q * 16 + 2 * tig;  // row gid
    const float* xs1 = xs0 + (size_t)8 * TT * 64;                              // row gid+8
    uint32_t* AsA = Asm + q * 128 + l * 4;    // uint4 slot (buffer 0)

    // flush mapping
    const int sF  = tid >> 3;
    const int ocF = tid & 7;

    float cc[4] = {0.f, 0.f, 0.f, 0.f};

    // prologue: stage x_0 into buffer 0, prefetch x_1
    float2 xr0, xr1, xr2, xr3;
    {
        const int tt0 = dir ? TT - 1 : 0;
        xr0 = *(const float2*)(xs0 + (size_t)tt0 * 64);
        xr1 = *(const float2*)(xs1 + (size_t)tt0 * 64);
        xr2 = *(const float2*)(xs0 + (size_t)tt0 * 64 + 8);
        xr3 = *(const float2*)(xs1 + (size_t)tt0 * 64 + 8);
        *(uint4*)AsA = make_uint4(bf2p(xr0), bf2p(xr1), bf2p(xr2), bf2p(xr3));
        if (TT > 1) {
            const int tt1 = dir ? TT - 2 : 1;
            xr0 = *(const float2*)(xs0 + (size_t)tt1 * 64);
            xr1 = *(const float2*)(xs1 + (size_t)tt1 * 64);
            xr2 = *(const float2*)(xs0 + (size_t)tt1 * 64 + 8);
            xr3 = *(const float2*)(xs1 + (size_t)tt1 * 64 + 8);
        }
    }
    __syncthreads();

    for (int t = 0; t < TT; t++) {
        const int tt = dir ? TT - 1 - t : t;
        const uint32_t* Acur = Asm + (t & 1) * 768;
        uint32_t*       Anxt = Asm + ((t + 1) & 1) * 768;

        // ---- MMA on A[t&1] ----
        float d[4][4];
        #pragma unroll
        for (int g = 0; g < 4; g++) {
            d[g][0] = bz[g].x; d[g][1] = bz[g].y;
            d[g][2] = bz[g].x; d[g][3] = bz[g].y;
        }
        #pragma unroll
        for (int kc = 0; kc < 6; kc++) {
            const uint4 a = *((const uint4*)Acur + kc * 32 + l);
            #pragma unroll
            for (int g = 0; g < 4; g++)
                mma_bf16(d[g], a, Br[kc][g][0], Br[kc][g][1]);
        }

        // ---- flush hout(t-1) to gmem (bf16 pairs) ----
        if (t > 0) {
            const int tprev = dir ? tt + 1 : tt - 1;
            const uint2 hv = *(const uint2*)&houtS[((t - 1) & 1) * 288 + sF * 18 + ocF * 2];
            *(uint2*)&g_h1b[((size_t)(ws + sF) * TT + tprev) * 32 + dir * 16 + ocF * 2] = hv;
        }

        // ---- stage x_{t+1} into A[(t+1)&1]; prefetch x_{t+2} ----
        if (t + 1 < TT) {
            *(uint4*)(Anxt + q * 128 + l * 4)
                = make_uint4(bf2p(xr0), bf2p(xr1), bf2p(xr2), bf2p(xr3));
            if (t + 2 < TT) {
                const int tt2 = dir ? tt - 2 : tt + 2;
                xr0 = *(const float2*)(xs0 + (size_t)tt2 * 64);
                xr1 = *(const float2*)(xs1 + (size_t)tt2 * 64);
                xr2 = *(const float2*)(xs0 + (size_t)tt2 * 64 + 8);
                xr3 = *(const float2*)(xs1 + (size_t)tt2 * 64 + 8);
            }
        }

        // ---- activations; h -> A[(t+1)&1] + houtS[t&1] ----
        uint32_t hp[2];
        #pragma unroll
        for (int rh = 0; rh < 2; rh++) {
            float h0, h1;
            {
                const int p = rh * 2;
                const float ig = sigx(d[0][p]);
                const float fg = sigx(d[1][p]);
                const float gg = tanhx(d[2][p]);
                const float og = sigx(d[3][p]);
                const float c  = fg * cc[p] + ig * gg;
                h0 = og * tanhx(c); cc[p] = c;
            }
            {
                const int p = rh * 2 + 1;
                const float ig = sigx(d[0][p]);
                const float fg = sigx(d[1][p]);
                const float gg = tanhx(d[2][p]);
                const float og = sigx(d[3][p]);
                const float c  = fg * cc[p] + ig * gg;
                h1 = og * tanhx(c); cc[p] = c;
            }
            hp[rh] = bf2(h0, h1);
            houtS[(t & 1) * 288 + (gid + 8 * rh) * 18 + q * 4 + tig] = hp[rh];
        }
        // h feedback: kc = 4+(q>>1), slots (q&1)*2 + {0,1}
        *(uint2*)(Anxt + (4 + (q >> 1)) * 128 + l * 4 + (q & 1) * 2)
            = make_uint2(hp[0], hp[1]);

        __syncthreads();
    }

    // final flush (t = TT-1)
    {
        const int tlast = dir ? 0 : TT - 1;
        const uint2 hv = *(const uint2*)&houtS[((TT - 1) & 1) * 288 + sF * 18 + ocF * 2];
        *(uint2*)&g_h1b[((size_t)(ws + sF) * TT + tlast) * 32 + dir * 16 + ocF * 2] = hv;
    }
}

// ================= layer 2: H=16, KIN=64, K=80 (KC=5), last-h only ===========
// Block = 128 thr = 2 pairs x 2 warps, pair owns 16 samples; grid (B/32, 2).
// Warp half: gate n-tiles g*2+half. B in regs. A double-buffered; one named
// pair barrier per step. Staging reads g_h1b (bf16) directly: pure u32 copies.
__global__ void __launch_bounds__(128) lstm2_mma(
    const float* __restrict__ W2f, const float* __restrict__ U2f, const float* __restrict__ b2f,
    const float* __restrict__ W2b, const float* __restrict__ U2b, const float* __restrict__ b2b)
{
    __shared__ uint32_t Bsm[5 * 8 * 32 * 2];                 // 10KB (init only)
    __shared__ __align__(16) uint32_t Asm[2 * 2 * 5 * 128];  // 10KB: [pair][buf][640]
    __shared__ float biasS[64];

    const int dir = blockIdx.y;
    const float* W    = dir ? W2b : W2f;
    const float* U    = dir ? U2b : U2f;
    const float* bias = dir ? b2b : b2f;

    const int tid  = threadIdx.x;
    const int wrp  = tid >> 5;
    const int l    = tid & 31;
    const int gid  = l >> 2;
    const int tig  = l & 3;
    const int pair = wrp >> 1;
    const int half = wrp & 1;
    const int barId = pair + 1;

    for (int idx = tid; idx < 5 * 8 * 32 * 2; idx += 128) {
        const int which = idx & 1;
        const int lane  = (idx >> 1) & 31;
        const int nt    = (idx >> 6) & 7;
        const int kc    = idx >> 9;
        const int k = kc * 16 + which * 8 + 2 * (lane & 3);
        const int n = nt * 8 + (lane >> 2);
        const float v0 = (k     < 64) ? W[k * 64 + n]       : U[(k - 64) * 64 + n];
        const float v1 = (k + 1 < 64) ? W[(k + 1) * 64 + n] : U[(k - 63) * 64 + n];
        Bsm[idx] = bf2(v0, v1);
    }
    if (tid < 64) biasS[tid] = bias[tid];
    // zero h regions of buffer 0 of both pairs (kc 4)
    for (int idx = tid; idx < 256; idx += 128) {
        const int pp = idx >> 7, ii = idx & 127;
        Asm[pp * 1280 + 512 + ii] = 0;
    }
    __syncthreads();

    uint32_t Br[5][4][2];
    #pragma unroll
    for (int kc = 0; kc < 5; kc++)
        #pragma unroll
        for (int g = 0; g < 4; g++) {
            const int base = ((kc * 8 + g * 2 + half) * 32 + l) * 2;
            Br[kc][g][0] = Bsm[base];
            Br[kc][g][1] = Bsm[base + 1];
        }

    float2 bz[4];
    #pragma unroll
    for (int g = 0; g < 4; g++) {
        const int col = g * 16 + half * 8 + 2 * tig;
        bz[g] = make_float2(biasS[col], biasS[col + 1]);
    }

    const int ws = (blockIdx.x * 2 + pair) * 16;
    uint32_t* Ap = Asm + pair * 1280;

    // staging: pair-thread pt -> (kc = pt>>4, u = pt&15 -> gid = u>>1, tp = u&1)
    const int pt   = tid & 63;
    const int kcS  = pt >> 4;
    const int gidS = (pt & 15) >> 1;
    const int tp   = pt & 1;
    const uint32_t* h0p = g_h1b + (size_t)(ws + gidS) * TT * 32 + kcS * 8 + 2 * tp;
    const uint32_t* h1p = h0p + (size_t)8 * TT * 32;
    const int j0 = gidS * 4 + 2 * tp;

    float cc[4] = {0.f, 0.f, 0.f, 0.f};

    uint2 lo0, lo1, hi0, hi1;
    {
        const int tt0 = dir ? TT - 1 : 0;
        lo0 = *(const uint2*)(h0p + (size_t)tt0 * 32);
        lo1 = *(const uint2*)(h1p + (size_t)tt0 * 32);
        hi0 = *(const uint2*)(h0p + (size_t)tt0 * 32 + 4);
        hi1 = *(const uint2*)(h1p + (size_t)tt0 * 32 + 4);
        *(uint4*)(Ap + kcS * 128 + j0 * 4)
            = make_uint4(lo0.x, lo1.x, hi0.x, hi1.x);
        *(uint4*)(Ap + kcS * 128 + (j0 + 1) * 4)
            = make_uint4(lo0.y, lo1.y, hi0.y, hi1.y);
        if (TT > 1) {
            const int tt1 = dir ? TT - 2 : 1;
            lo0 = *(const uint2*)(h0p + (size_t)tt1 * 32);
            lo1 = *(const uint2*)(h1p + (size_t)tt1 * 32);
            hi0 = *(const uint2*)(h0p + (size_t)tt1 * 32 + 4);
            hi1 = *(const uint2*)(h1p + (size_t)tt1 * 32 + 4);
        }
    }
    __syncthreads();

    for (int t = 0; t < TT; t++) {
        const int tt = dir ? TT - 1 - t : t;
        const uint32_t* Acur = Ap + (t & 1) * 640;
        uint32_t*       Anxt = Ap + ((t + 1) & 1) * 640;

        float d[4][4];
        #pragma unroll
        for (int g = 0; g < 4; g++) {
            d[g][0] = bz[g].x; d[g][1] = bz[g].y;
            d[g][2] = bz[g].x; d[g][3] = bz[g].y;
        }
        #pragma unroll
        for (int kc = 0; kc < 5; kc++) {
            const uint4 a = *((const uint4*)Acur + kc * 32 + l);
            #pragma unroll
            for (int g = 0; g < 4; g++)
                mma_bf16(d[g], a, Br[kc][g][0], Br[kc][g][1]);
        }

        if (t + 1 < TT) {
            *(uint4*)(Anxt + kcS * 128 + j0 * 4)
                = make_uint4(lo0.x, lo1.x, hi0.x, hi1.x);
            *(uint4*)(Anxt + kcS * 128 + (j0 + 1) * 4)
                = make_uint4(lo0.y, lo1.y, hi0.y, hi1.y);
            if (t + 2 < TT) {
                const int tt2 = dir ? tt - 2 : tt + 2;
                lo0 = *(const uint2*)(h0p + (size_t)tt2 * 32);
                lo1 = *(const uint2*)(h1p + (size_t)tt2 * 32);
                hi0 = *(const uint2*)(h0p + (size_t)tt2 * 32 + 4);
                hi1 = *(const uint2*)(h1p + (size_t)tt2 * 32 + 4);
            }
        }

        uint32_t hp[2];
        float hlast[4];
        #pragma unroll
        for (int rh = 0; rh < 2; rh++) {
            float h0, h1;
            {
                const int p = rh * 2;
                const float ig = sigx(d[0][p]);
                const float fg = sigx(d[1][p]);
                const float gg = tanhx(d[2][p]);
                const float og = sigx(d[3][p]);
                const float c  = fg * cc[p] + ig * gg;
                h0 = og * tanhx(c); cc[p] = c;
            }
            {
                const int p = rh * 2 + 1;
                const float ig = sigx(d[0][p]);
                const float fg = sigx(d[1][p]);
                const float gg = tanhx(d[2][p]);
                const float og = sigx(d[3][p]);
                const float c  = fg * cc[p] + ig * gg;
                h1 = og * tanhx(c); cc[p] = c;
            }
            hp[rh] = bf2(h0, h1);
            hlast[rh * 2] = h0; hlast[rh * 2 + 1] = h1;
        }
        *(uint2*)(Anxt + 4 * 128 + l * 4 + half * 2) = make_uint2(hp[0], hp[1]);

        if (t == TT - 1) {
            #pragma unroll
            for (int rh = 0; rh < 2; rh++) {
                const int e0 = half * 8 + 2 * tig;
                *(float2*)&g_h2[(ws + gid + 8 * rh) * 32 + dir * 16 + e0]
                    = make_float2(hlast[rh * 2], hlast[rh * 2 + 1]);
            }
        }

        BARP(barId);
    }
}

// ================= head: dense(8)+swish, dense(2)+sigmoid ================
__device__ __forceinline__ float sigf(float x) { return 1.0f / (1.0f + __expf(-x)); }

__global__ void head_kernel(
    const float* __restrict__ W3, const float* __restrict__ b3,
    const float* __restrict__ W4, const float* __restrict__ b4,
    float* __restrict__ out, int B)
{
    const int b = blockIdx.x * blockDim.x + threadIdx.x;
    if (b >= B) return;

    float xvv[32];
    #pragma unroll
    for (int i = 0; i < 32; i++) xvv[i] = g_h2[b * 32 + i];

    float y[8];
    #pragma unroll
    for (int o = 0; o < 8; o++) {
        float acc = b3[o];
        #pragma unroll
        for (int k = 0; k < 32; k++)
            acc = fmaf(xvv[k], W3[k * 8 + o], acc);
        y[o] = acc * sigf(acc);
    }

    #pragma unroll
    for (int m = 0; m < 2; m++) {
        float acc = b4[m];
        #pragma unroll
        for (int o = 0; o < 8; o++)
            acc = fmaf(y[o], W4[o * 2 + m], acc);
        out[b * 2 + m] = sigf(acc);
    }
}

// ================= launch ================
extern "C" void kernel_launch(void* const* d_in, const int* in_sizes, int n_in,
                              void* d_out, int out_size)
{
    const float* x   = (const float*)d_in[0];
    const float* W1f = (const float*)d_in[1];
    const float* U1f = (const float*)d_in[2];
    const float* b1f = (const float*)d_in[3];
    const float* W1b = (const float*)d_in[4];
    const float* U1b = (const float*)d_in[5];
    const float* b1b = (const float*)d_in[6];
    const float* W2f = (const float*)d_in[7];
    const float* U2f = (const float*)d_in[8];
    const float* b2f = (const float*)d_in[9];
    const float* W2b = (const float*)d_in[10];
    const float* U2b = (const float*)d_in[11];
    const float* b2b = (const float*)d_in[12];
    const float* W3  = (const float*)d_in[13];
    const float* b3  = (const float*)d_in[14];
    const float* W4  = (const float*)d_in[15];
    const float* b4  = (const float*)d_in[16];
    float* out = (float*)d_out;

    const int B = in_sizes[0] / (TT * 64);   // 4096

    lstm1_mma<<<dim3(B / 16, 2), 128>>>(x, W1f, U1f, b1f, W1b, U1b, b1b);
    lstm2_mma<<<dim3(B / 32, 2), 128>>>(W2f, U2f, b2f, W2b, U2b, b2b);
    head_kernel<<<(B + 255) / 256, 256>>>(W3, b3, W4, b4, out, B);
}